// round 2
// baseline (speedup 1.0000x reference)
#include <cuda_runtime.h>
#include <math.h>

#define BB 256
#define TT 512
#define NN 128
#define GO_IDX 1
#define EOS_IDX 2
#define NEGV -10000.0f
#define TS_STRIDE 129

// dynamic smem layout (bytes):
//   float ts[NN*TS_STRIDE]   : 66048
//   float alpha[NN]          : 512
//   float partv[2*NN]        : 1024
//   int   parti[2*NN]        : 1024
//   float red[32]            : 128
//   uchar bp[TT*NN]          : 65536
#define SMEM_BYTES (66048 + 512 + 1024 + 1024 + 128 + 65536)

__device__ __forceinline__ float warp_max(float v) {
    v = fmaxf(v, __shfl_xor_sync(0xffffffffu, v, 16));
    v = fmaxf(v, __shfl_xor_sync(0xffffffffu, v, 8));
    v = fmaxf(v, __shfl_xor_sync(0xffffffffu, v, 4));
    v = fmaxf(v, __shfl_xor_sync(0xffffffffu, v, 2));
    v = fmaxf(v, __shfl_xor_sync(0xffffffffu, v, 1));
    return v;
}
__device__ __forceinline__ float warp_sum(float v) {
    v += __shfl_xor_sync(0xffffffffu, v, 16);
    v += __shfl_xor_sync(0xffffffffu, v, 8);
    v += __shfl_xor_sync(0xffffffffu, v, 4);
    v += __shfl_xor_sync(0xffffffffu, v, 2);
    v += __shfl_xor_sync(0xffffffffu, v, 1);
    return v;
}

__global__ __launch_bounds__(256, 1)
void viterbi_kernel(const float* __restrict__ unaries,
                    const float* __restrict__ trans,
                    const void* __restrict__ lengths_raw,
                    float* __restrict__ out,
                    int out_size)
{
    extern __shared__ unsigned char smem[];
    float* ts    = (float*)smem;                  // NN*TS_STRIDE
    float* alpha = ts + NN * TS_STRIDE;           // NN
    float* partv = alpha + NN;                    // 2*NN
    int*   parti = (int*)(partv + 2 * NN);        // 2*NN
    float* red   = (float*)(parti + 2 * NN);      // 32
    unsigned char* bp = (unsigned char*)(red + 32); // TT*NN

    const int b    = blockIdx.x;
    const int tid  = threadIdx.x;
    const int lane = tid & 31;
    const int wrp  = tid >> 5;
    const int j    = tid & (NN - 1);
    const int h    = tid >> 7;            // prev-half

    // ---- length (auto-detect int64 vs int32: lengths are in [T/2, T], never 0) ----
    const int* li = (const int*)lengths_raw;
    int len;
    if (li[1] == 0) len = (int)(((const long long*)lengths_raw)[b]);
    else            len = li[b];
    if (len < 1) len = 1;
    if (len > TT) len = TT;

    // ---- stage trans[cur][prev] into padded smem (bank-conflict-free) ----
    for (int idx = tid; idx < NN * NN; idx += 256) {
        int c = idx >> 7, p = idx & (NN - 1);
        ts[c * TS_STRIDE + p] = trans[idx];
    }
    // ---- init alpha: log_softmax of one-hot-at-GO is an exact identity in f32 ----
    if (tid < NN) alpha[tid] = (tid == GO_IDX) ? 0.0f : NEGV;
    __syncthreads();

    const float* ub = unaries + (size_t)b * TT * NN;
    const float* tsj = ts + j * TS_STRIDE + (h << 6);
    const float* ap  = alpha + (h << 6);
    const float BIGNEG = -3.402823466e38f;

    for (int t = 0; t < len; ++t) {
        // ======== log_softmax(unaries[b,t,:]) ========
        float u = (tid < NN) ? ub[t * NN + tid] : BIGNEG;
        float wm = warp_max(u);
        if (lane == 0) red[wrp] = wm;
        __syncthreads();
        if (tid == 0) {
            float m = red[0];
            #pragma unroll
            for (int k = 1; k < 8; ++k) m = fmaxf(m, red[k]);
            red[16] = m;
        }
        __syncthreads();
        float m = red[16];
        float e = (tid < NN) ? expf(u - m) : 0.0f;
        float ws = warp_sum(e);
        if (lane == 0) red[8 + wrp] = ws;
        __syncthreads();
        if (tid == 0) {
            float s = red[8];
            #pragma unroll
            for (int k = 1; k < 8; ++k) s += red[8 + k];
            red[17] = logf(s);
        }
        __syncthreads();
        float pvj = (u - m) - red[17];   // thread tid<NN holds probv for tag tid

        // ======== max/argmax over 64 prev (4 independent chains) ========
        float b0 = BIGNEG, b1 = BIGNEG, b2 = BIGNEG, b3 = BIGNEG;
        int i0 = 0, i1 = 1, i2 = 2, i3 = 3;
        #pragma unroll
        for (int p = 0; p < 64; p += 4) {
            float v0 = ap[p + 0] + tsj[p + 0];
            float v1 = ap[p + 1] + tsj[p + 1];
            float v2 = ap[p + 2] + tsj[p + 2];
            float v3 = ap[p + 3] + tsj[p + 3];
            if (v0 > b0) { b0 = v0; i0 = p + 0; }
            if (v1 > b1) { b1 = v1; i1 = p + 1; }
            if (v2 > b2) { b2 = v2; i2 = p + 2; }
            if (v3 > b3) { b3 = v3; i3 = p + 3; }
        }
        // merge accumulators, first-max-index tie semantics (== jnp.argmax)
        float mva; int mia;
        if (b1 > b0 || (b1 == b0 && i1 < i0)) { mva = b1; mia = i1; } else { mva = b0; mia = i0; }
        float mvb; int mib;
        if (b3 > b2 || (b3 == b2 && i3 < i2)) { mvb = b3; mib = i3; } else { mvb = b2; mib = i2; }
        if (mvb > mva || (mvb == mva && mib < mia)) { mva = mvb; mia = mib; }
        mia += (h << 6);
        partv[h * NN + j] = mva;
        parti[h * NN + j] = mia;
        __syncthreads();   // partials ready; all alpha reads for this t are done

        if (tid < NN) {
            float v0 = partv[j], v1 = partv[NN + j];
            float mv; int mi;
            if (v1 > v0) { mv = v1; mi = parti[NN + j]; }   // tie -> half 0 (lower idx)
            else         { mv = v0; mi = parti[j]; }
            bp[t * NN + j] = (unsigned char)mi;
            alpha[j] = mv + pvj;
        }
        __syncthreads();   // alpha ready for next step
    }

    // ======== terminal + backtrace ========
    if (tid < NN) partv[tid] = alpha[tid] + ts[EOS_IDX * TS_STRIDE + tid];
    __syncthreads();

    if (tid == 0) {
        float bv = partv[0]; int bi = 0;
        #pragma unroll 4
        for (int p = 1; p < NN; ++p) {
            if (partv[p] > bv) { bv = partv[p]; bi = p; }
        }
        if ((size_t)(BB * TT + b) < (size_t)out_size)
            out[(size_t)BB * TT + b] = bv;           // path score
        int cur = bi;
        float* po = out + (size_t)b * TT;
        for (int t = len - 1; t >= 0; --t) {
            po[t] = (float)cur;
            if (t > 0) cur = bp[t * NN + cur];
        }
    }
    // zero tail (t >= len)
    for (int t = len + tid; t < TT; t += 256)
        out[(size_t)b * TT + t] = 0.0f;
}

extern "C" void kernel_launch(void* const* d_in, const int* in_sizes, int n_in,
                              void* d_out, int out_size)
{
    const float* unaries = (const float*)d_in[0];
    const float* trans   = (const float*)d_in[1];
    const void*  lengths = d_in[2];
    float* out = (float*)d_out;

    cudaFuncSetAttribute(viterbi_kernel,
                         cudaFuncAttributeMaxDynamicSharedMemorySize, SMEM_BYTES);
    viterbi_kernel<<<BB, 256, SMEM_BYTES>>>(unaries, trans, lengths, out, out_size);
}

// round 5
// speedup vs baseline: 2.6886x; 2.6886x over previous
#include <cuda_runtime.h>
#include <math.h>

#define BB 256
#define TT 512
#define NN 128
#define GO_IDX 1
#define EOS_IDX 2
#define NEGV -10000.0f

// global scratch (static __device__ arrays are allowed)
__device__ float2 g_mls[BB * TT];   // per (b,t): {max, log-sum-exp(shifted)}
__device__ int    g_assign[BB];     // blockIdx -> batch item (LPT pairing)

// ---------------- kernel A: per-row softmax stats ----------------
__global__ __launch_bounds__(256)
void softmax_pre(const float* __restrict__ unaries)
{
    int r = blockIdx.x * 8 + (threadIdx.x >> 5);   // row = b*TT + t
    int lane = threadIdx.x & 31;
    if (r >= BB * TT) return;
    const float* u = unaries + (size_t)r * NN;
    float x0 = u[lane], x1 = u[lane + 32], x2 = u[lane + 64], x3 = u[lane + 96];
    float m = fmaxf(fmaxf(x0, x1), fmaxf(x2, x3));
    #pragma unroll
    for (int o = 16; o > 0; o >>= 1) m = fmaxf(m, __shfl_xor_sync(0xffffffffu, m, o));
    float e = expf(x0 - m) + expf(x1 - m) + expf(x2 - m) + expf(x3 - m);
    #pragma unroll
    for (int o = 16; o > 0; o >>= 1) e += __shfl_xor_sync(0xffffffffu, e, o);
    if (lane == 0) g_mls[r] = make_float2(m, logf(e));
}

// ---------------- kernel B: sort lengths desc, build LPT assignment ----------------
#define NSM 152   // GB300 SMs; co-resident pairing: bid k with bid k+NSM
__global__ __launch_bounds__(256)
void prep_assign(const void* __restrict__ lengths_raw)
{
    __shared__ long long key[BB];
    int tid = threadIdx.x;
    const int* li = (const int*)lengths_raw;
    int len = (li[1] == 0) ? (int)(((const long long*)lengths_raw)[tid]) : li[tid];
    key[tid] = ((long long)len << 32) | (long long)tid;
    __syncthreads();
    for (int k = 2; k <= BB; k <<= 1) {
        for (int jj = k >> 1; jj > 0; jj >>= 1) {
            int ixj = tid ^ jj;
            if (ixj > tid) {
                long long a = key[tid], c = key[ixj];
                bool desc = ((tid & k) == 0);
                if (desc ? (a < c) : (a > c)) { key[tid] = c; key[ixj] = a; }
            }
            __syncthreads();
        }
    }
    // ranks sorted desc by length. bid k (k<NSM) -> rank k (longest items spread
    // across SMs); bid NSM+k -> rank BB-1-k, i.e. rank = NSM + BB - 1 - tid.
    int rank = (tid < NSM) ? tid : (NSM + BB - 1 - tid);
    rank = min(BB - 1, max(0, rank));
    g_assign[tid] = (int)(key[rank] & 0xffffffffLL);
}

// ---------------- kernel C: Viterbi DP ----------------
// smem: bp 65536 (trans staging first) | alpha 512 | partv 1024 | parti 1024 | mls 4096
#define SMEM_BYTES (65536 + 512 + 1024 + 1024 + 4096)

__global__ __launch_bounds__(256, 2)
void viterbi4(const float* __restrict__ unaries,
              const float* __restrict__ trans,
              const void* __restrict__ lengths_raw,
              float* __restrict__ out,
              int out_size)
{
    extern __shared__ unsigned char smem[];
    unsigned char* bp = smem;                       // TT*NN
    float*  alpha = (float*)(smem + 65536);         // NN
    float*  partv = alpha + NN;                     // 2*NN
    int*    parti = (int*)(partv + 2 * NN);         // 2*NN
    float2* mlsS  = (float2*)(parti + 2 * NN);      // TT

    int b = g_assign[blockIdx.x];
    b = min(BB - 1, max(0, b));                     // never let a bad assign become OOB
    const int tid = threadIdx.x;
    const int j   = tid & (NN - 1);
    const int h   = tid >> 7;

    const int* li = (const int*)lengths_raw;
    int len = (li[1] == 0) ? (int)(((const long long*)lengths_raw)[b]) : li[b];
    len = max(1, min(TT, len));

    // stage trans coalesced -> regs; load per-step softmax stats
    float* ts = (float*)bp;
    for (int idx = tid; idx < NN * NN; idx += 256) ts[idx] = trans[idx];
    for (int idx = tid; idx < TT; idx += 256) mlsS[idx] = g_mls[b * TT + idx];
    if (tid < NN) alpha[tid] = (tid == GO_IDX) ? 0.0f : NEGV;  // exact log_softmax identity
    __syncthreads();

    float tr[64];
    {
        const float4* base = (const float4*)(ts + j * NN + (h << 6));
        #pragma unroll
        for (int k = 0; k < 16; ++k) {
            float4 v = base[k];
            tr[4*k+0] = v.x; tr[4*k+1] = v.y; tr[4*k+2] = v.z; tr[4*k+3] = v.w;
        }
    }
    __syncthreads();   // done reading ts before bp overwrites it

    const float* ub = unaries + (size_t)b * TT * NN;
    const float* ap = alpha + (h << 6);
    const float BIG = -3.402823466e38f;

    float ucur = (tid < NN) ? ub[j] : 0.0f;

    for (int t = 0; t < len; ++t) {
        float unext = 0.0f;
        if (tid < NN && t + 1 < len) unext = ub[(t + 1) * NN + j];  // prefetch

        // 8 independent argmax chains over blocks of 8 prev
        float mv[8]; int mi[8];
        #pragma unroll
        for (int c = 0; c < 8; ++c) { mv[c] = BIG; mi[c] = c * 8; }
        #pragma unroll
        for (int q = 0; q < 16; ++q) {
            float4 a4 = ((const float4*)ap)[q];     // broadcast LDS.128
            const int c = q >> 1;
            const int p = q * 4;
            float v0 = a4.x + tr[p+0];
            float v1 = a4.y + tr[p+1];
            float v2 = a4.z + tr[p+2];
            float v3 = a4.w + tr[p+3];
            if (v0 > mv[c]) { mv[c] = v0; mi[c] = p+0; }
            if (v1 > mv[c]) { mv[c] = v1; mi[c] = p+1; }
            if (v2 > mv[c]) { mv[c] = v2; mi[c] = p+2; }
            if (v3 > mv[c]) { mv[c] = v3; mi[c] = p+3; }
        }
        float bv = mv[0]; int bi = mi[0];
        #pragma unroll
        for (int c = 1; c < 8; ++c)
            if (mv[c] > bv) { bv = mv[c]; bi = mi[c]; }   // strict > keeps first index

        partv[(h << 7) + j] = bv;
        parti[(h << 7) + j] = bi + (h << 6);
        __syncthreads();

        if (tid < NN) {
            float v0 = partv[j], v1 = partv[NN + j];
            float m; int i_;
            if (v1 > v0) { m = v1; i_ = parti[NN + j]; }  // tie -> half 0 (lower idx)
            else         { m = v0; i_ = parti[j]; }
            bp[t * NN + j] = (unsigned char)i_;
            float2 c2 = mlsS[t];
            alpha[j] = m + ((ucur - c2.x) - c2.y);        // normalized probv, round-1 op order
        }
        ucur = unext;
        __syncthreads();
    }

    // terminal + backtrace
    if (tid < NN) partv[tid] = alpha[tid] + trans[EOS_IDX * NN + tid];
    __syncthreads();

    if (tid == 0) {
        float bv = partv[0]; int bi = 0;
        #pragma unroll 4
        for (int p = 1; p < NN; ++p)
            if (partv[p] > bv) { bv = partv[p]; bi = p; }
        out[(size_t)BB * TT + b] = bv;
        int cur = bi;
        float* po = out + (size_t)b * TT;
        for (int t = len - 1; t >= 0; --t) {
            po[t] = (float)cur;
            if (t > 0) cur = bp[t * NN + cur];
        }
    }
    for (int t = len + tid; t < TT; t += 256)
        out[(size_t)b * TT + t] = 0.0f;
}

extern "C" void kernel_launch(void* const* d_in, const int* in_sizes, int n_in,
                              void* d_out, int out_size)
{
    const float* unaries = (const float*)d_in[0];
    const float* trans   = (const float*)d_in[1];
    const void*  lengths = d_in[2];
    float* out = (float*)d_out;

    softmax_pre<<<(BB * TT + 7) / 8, 256>>>(unaries);
    prep_assign<<<1, 256>>>(lengths);
    cudaFuncSetAttribute(viterbi4,
                         cudaFuncAttributeMaxDynamicSharedMemorySize, SMEM_BYTES);
    viterbi4<<<BB, 256, SMEM_BYTES>>>(unaries, trans, lengths, out, out_size);
}